// round 16
// baseline (speedup 1.0000x reference)
#include <cuda_runtime.h>
#include <cuda_bf16.h>
#include <cstdint>

// Problem constants
#define BATCH  4
#define SEQ    2048
#define DMODEL 1024
#define NHEAD  16
#define DHEAD  64
#define MTOT   (BATCH * SEQ)   // 8192 rows
#define KDIM   DMODEL

// ---------------------------------------------------------------------------
// Scratch (__device__ globals — the sanctioned no-alloc path). All bf16 hi/lo.
// ---------------------------------------------------------------------------
__device__ __nv_bfloat16 g_xqHi[(size_t)MTOT * DMODEL];
__device__ __nv_bfloat16 g_xqLo[(size_t)MTOT * DMODEL];
__device__ __nv_bfloat16 g_xkHi[(size_t)MTOT * DMODEL];
__device__ __nv_bfloat16 g_xkLo[(size_t)MTOT * DMODEL];
__device__ __nv_bfloat16 g_xvHi[(size_t)MTOT * DMODEL];
__device__ __nv_bfloat16 g_xvLo[(size_t)MTOT * DMODEL];
__device__ __nv_bfloat16 g_wqHi[(size_t)DMODEL * DMODEL];
__device__ __nv_bfloat16 g_wqLo[(size_t)DMODEL * DMODEL];
__device__ __nv_bfloat16 g_wkHi[(size_t)DMODEL * DMODEL];
__device__ __nv_bfloat16 g_wkLo[(size_t)DMODEL * DMODEL];
__device__ __nv_bfloat16 g_wvHi[(size_t)DMODEL * DMODEL];
__device__ __nv_bfloat16 g_wvLo[(size_t)DMODEL * DMODEL];
__device__ __nv_bfloat16 g_wdHi[(size_t)DMODEL * DMODEL];
__device__ __nv_bfloat16 g_wdLo[(size_t)DMODEL * DMODEL];
__device__ __nv_bfloat16 g_qHi[(size_t)MTOT * DMODEL];
__device__ __nv_bfloat16 g_qLo[(size_t)MTOT * DMODEL];
__device__ __nv_bfloat16 g_kHi[(size_t)MTOT * DMODEL];
__device__ __nv_bfloat16 g_kLo[(size_t)MTOT * DMODEL];
__device__ __nv_bfloat16 g_vHi[(size_t)MTOT * DMODEL];
__device__ __nv_bfloat16 g_vLo[(size_t)MTOT * DMODEL];
__device__ __nv_bfloat16 g_cHi[(size_t)MTOT * DMODEL];
__device__ __nv_bfloat16 g_cLo[(size_t)MTOT * DMODEL];

// ---------------------------------------------------------------------------
// Helpers (baseline compute_103 PTX only — no tcgen05/TMEM in this harness)
// ---------------------------------------------------------------------------
__device__ __forceinline__ uint32_t smem_u32(const void* p) {
    uint32_t a;
    asm("{ .reg .u64 t; cvta.to.shared.u64 t, %1; cvt.u32.u64 %0, t; }"
        : "=r"(a) : "l"(p));
    return a;
}
__device__ __forceinline__ void ldsm4(uint32_t* r, uint32_t addr) {
    asm volatile("ldmatrix.sync.aligned.m8n8.x4.shared.b16 {%0,%1,%2,%3}, [%4];"
                 : "=r"(r[0]), "=r"(r[1]), "=r"(r[2]), "=r"(r[3]) : "r"(addr));
}
__device__ __forceinline__ void ldsm4t(uint32_t* r, uint32_t addr) {
    asm volatile("ldmatrix.sync.aligned.m8n8.x4.trans.shared.b16 {%0,%1,%2,%3}, [%4];"
                 : "=r"(r[0]), "=r"(r[1]), "=r"(r[2]), "=r"(r[3]) : "r"(addr));
}
__device__ __forceinline__ void mma16816(float* d, const uint32_t* a, const uint32_t* b) {
    asm volatile(
        "mma.sync.aligned.m16n8k16.row.col.f32.bf16.bf16.f32 "
        "{%0,%1,%2,%3}, {%4,%5,%6,%7}, {%8,%9}, {%0,%1,%2,%3};"
        : "+f"(d[0]), "+f"(d[1]), "+f"(d[2]), "+f"(d[3])
        : "r"(a[0]), "r"(a[1]), "r"(a[2]), "r"(a[3]), "r"(b[0]), "r"(b[1]));
}
__device__ __forceinline__ uint32_t pack_bf2(__nv_bfloat16 a, __nv_bfloat16 b) {
    __nv_bfloat162 t = __halves2bfloat162(a, b);
    return *(uint32_t*)&t;
}
__device__ __forceinline__ void cpasync16(uint32_t dst, const void* src) {
    asm volatile("cp.async.ca.shared.global [%0], [%1], 16;"
                 :: "r"(dst), "l"(src) : "memory");
}
__device__ __forceinline__ void cp_commit() {
    asm volatile("cp.async.commit_group;" ::: "memory");
}
__device__ __forceinline__ void cp_wait0() {
    asm volatile("cp.async.wait_group 0;" ::: "memory");
}
__device__ __forceinline__ void cp_wait1() {
    asm volatile("cp.async.wait_group 1;" ::: "memory");
}

// exp(x/8) for x <= 0, MUFU-free: 2^(x*log2e/8), deg-4 poly.
__device__ __forceinline__ float fexp8(float x) {
    float t = fmaxf(x * 0.18033688011112043f, -126.0f);
    float r = t + 12582912.0f;
    int   n = __float_as_int(r) - 0x4B400000;
    float f = t - (r - 12582912.0f);
    float p = fmaf(f, 0.0096181291f, 0.0555041087f);
    p = fmaf(f, p, 0.2402265069f);
    p = fmaf(f, p, 0.6931471806f);
    p = fmaf(f, p, 1.0f);
    return __int_as_float((n + 127) << 23) * p;
}

// ---------------------------------------------------------------------------
// fp32 -> (hi, lo) bf16 split: merged launches (blockIdx.y selects operand)
// ---------------------------------------------------------------------------
struct SplitArgs {
    const float* x;
    __nv_bfloat16* hi;
    __nv_bfloat16* lo;
};

__device__ __forceinline__ void split_body(const SplitArgs& s, int i) {
    float4 v = ((const float4*)s.x)[i];
    __nv_bfloat16 h0 = __float2bfloat16_rn(v.x);
    __nv_bfloat16 h1 = __float2bfloat16_rn(v.y);
    __nv_bfloat16 h2 = __float2bfloat16_rn(v.z);
    __nv_bfloat16 h3 = __float2bfloat16_rn(v.w);
    uint2 hv, lv;
    hv.x = pack_bf2(h0, h1);
    hv.y = pack_bf2(h2, h3);
    lv.x = pack_bf2(__float2bfloat16_rn(v.x - __bfloat162float(h0)),
                    __float2bfloat16_rn(v.y - __bfloat162float(h1)));
    lv.y = pack_bf2(__float2bfloat16_rn(v.z - __bfloat162float(h2)),
                    __float2bfloat16_rn(v.w - __bfloat162float(h3)));
    ((uint2*)s.hi)[i] = hv;
    ((uint2*)s.lo)[i] = lv;
}

__global__ __launch_bounds__(256)
void split3(SplitArgs s0, SplitArgs s1, SplitArgs s2, int n4)
{
    int i = blockIdx.x * 256 + threadIdx.x;
    if (i >= n4) return;
    SplitArgs s = (blockIdx.y == 0) ? s0 : ((blockIdx.y == 1) ? s1 : s2);
    split_body(s, i);
}

__global__ __launch_bounds__(256)
void split4(SplitArgs s0, SplitArgs s1, SplitArgs s2, SplitArgs s3, int n4)
{
    int i = blockIdx.x * 256 + threadIdx.x;
    if (i >= n4) return;
    SplitArgs s = (blockIdx.y == 0) ? s0 :
                  ((blockIdx.y == 1) ? s1 : ((blockIdx.y == 2) ? s2 : s3));
    split_body(s, i);
}

// ---------------------------------------------------------------------------
// GEMM via mma.sync bf16 3-term split, 3-stage cp.async pipeline, ONE barrier
// per chunk. grid.z selects the operand set (merged Q/K/V projections).
// Epilogue: yf != nullptr -> fp32 out; else bf16 hi/lo out.
//
// Buffer (48KB, x3 stages): Ahi@0 Alo@12288 Bhi@24576 Blo@36864; each term =
// 2 k-slabs (16 k) of 128 rows x 32B, row stride 48B (verified R12 layout).
// ---------------------------------------------------------------------------
#define GBUF 49152
#define GEMM_SMEM (3 * GBUF)
#define NCHUNK (KDIM / 32)

struct GemmArgs {
    const __nv_bfloat16 *xh, *xl, *wh, *wl;
    const float* bias;
    float* yf;
    __nv_bfloat16 *yh, *yl;
};

__global__ __launch_bounds__(256)
void gemm_mma3(GemmArgs A0, GemmArgs A1, GemmArgs A2)
{
    extern __shared__ char smem[];
    const uint32_t sb = smem_u32(smem);
    GemmArgs ar = (blockIdx.z == 0) ? A0 : ((blockIdx.z == 1) ? A1 : A2);

    const int tid  = threadIdx.x;
    const int lane = tid & 31, wid = tid >> 5;
    const int wm = wid & 3;
    const int wn = wid >> 2;
    const int bm = blockIdx.y * 128, bn = blockIdx.x * 128;

    const int lr = tid >> 1;
    const int h  = tid & 1;
    const size_t rowA = (size_t)(bm + lr) * KDIM;
    const size_t rowB = (size_t)(bn + lr) * KDIM;
    const uint32_t dbase = lr * 48 + h * 16;

    const uint32_t a_off = ((lane & 7) + ((lane >> 3) & 1) * 8) * 48 + ((lane >> 4) & 1) * 16;
    const uint32_t b_off = ((lane & 7) + ((lane >> 4) & 1) * 8) * 48 + ((lane >> 3) & 1) * 16;

    float acc[2][8][4];
#pragma unroll
    for (int mt = 0; mt < 2; mt++)
#pragma unroll
        for (int nt = 0; nt < 8; nt++)
#pragma unroll
            for (int e = 0; e < 4; e++) acc[mt][nt][e] = 0.f;

    auto issue = [&](int c, int bufIdx) {
        const uint32_t bb = sb + bufIdx * GBUF;
        const int k0 = c * 32 + h * 8;
#pragma unroll
        for (int s = 0; s < 2; s++) {
            uint32_t d = bb + s * 6144 + dbase;
            int kk = k0 + s * 16;
            cpasync16(d,         ar.xh + rowA + kk);
            cpasync16(d + 12288, ar.xl + rowA + kk);
            cpasync16(d + 24576, ar.wh + rowB + kk);
            cpasync16(d + 36864, ar.wl + rowB + kk);
        }
        cp_commit();
    };

    issue(0, 0);
    issue(1, 1);

    for (int c = 0; c < NCHUNK; c++) {
        if (c + 1 < NCHUNK) cp_wait1(); else cp_wait0();
        __syncthreads();     // chunk c resident; all warps past chunk c-1 reads

        if (c + 2 < NCHUNK) issue(c + 2, (c + 2) % 3);

        const uint32_t bufb = sb + (c % 3) * GBUF;
#pragma unroll
        for (int s = 0; s < 2; s++) {
            const uint32_t slab = bufb + s * 6144;
            uint32_t aH[2][4], aL[2][4], bH[4][4], bL[4][4];
#pragma unroll
            for (int mt = 0; mt < 2; mt++) {
                uint32_t ad = slab + (uint32_t)(wm * 32 + mt * 16) * 48 + a_off;
                ldsm4(aH[mt], ad);
                ldsm4(aL[mt], ad + 12288);
            }
#pragma unroll
            for (int p = 0; p < 4; p++) {
                uint32_t bd = slab + 24576 + (uint32_t)(wn * 64 + p * 16) * 48 + b_off;
                ldsm4(bH[p], bd);
                ldsm4(bL[p], bd + 12288);
            }
#pragma unroll
            for (int mt = 0; mt < 2; mt++)
#pragma unroll
                for (int p = 0; p < 4; p++)
#pragma unroll
                    for (int hlf = 0; hlf < 2; hlf++) {
                        const int nt = p * 2 + hlf;
                        mma16816(acc[mt][nt], aH[mt], &bH[p][hlf * 2]);
                        mma16816(acc[mt][nt], aH[mt], &bL[p][hlf * 2]);
                        mma16816(acc[mt][nt], aL[mt], &bH[p][hlf * 2]);
                    }
        }
        // no trailing barrier: next iteration's barrier (after wait) protects
        // the buffer that iteration's issue() will overwrite.
    }

    const int er = bm + wm * 32 + (lane >> 2);
    const int ec = bn + wn * 64 + (lane & 3) * 2;
#pragma unroll
    for (int mt = 0; mt < 2; mt++)
#pragma unroll
        for (int nt = 0; nt < 8; nt++) {
            int row = er + mt * 16;
            int col = ec + nt * 8;
            float2 bv = *(const float2*)(ar.bias + col);
            float y00 = acc[mt][nt][0] + bv.x, y01 = acc[mt][nt][1] + bv.y;
            float y10 = acc[mt][nt][2] + bv.x, y11 = acc[mt][nt][3] + bv.y;
            if (ar.yf) {
                *(float2*)(ar.yf + (size_t)row * DMODEL + col) = make_float2(y00, y01);
                *(float2*)(ar.yf + (size_t)(row + 8) * DMODEL + col) = make_float2(y10, y11);
            } else {
                __nv_bfloat16 h00 = __float2bfloat16_rn(y00), h01 = __float2bfloat16_rn(y01);
                __nv_bfloat16 h10 = __float2bfloat16_rn(y10), h11 = __float2bfloat16_rn(y11);
                *(uint32_t*)(ar.yh + (size_t)row * DMODEL + col)       = pack_bf2(h00, h01);
                *(uint32_t*)(ar.yh + (size_t)(row + 8) * DMODEL + col) = pack_bf2(h10, h11);
                *(uint32_t*)(ar.yl + (size_t)row * DMODEL + col) = pack_bf2(
                    __float2bfloat16_rn(y00 - __bfloat162float(h00)),
                    __float2bfloat16_rn(y01 - __bfloat162float(h01)));
                *(uint32_t*)(ar.yl + (size_t)(row + 8) * DMODEL + col) = pack_bf2(
                    __float2bfloat16_rn(y10 - __bfloat162float(h10)),
                    __float2bfloat16_rn(y11 - __bfloat162float(h11)));
            }
        }
}

// ---------------------------------------------------------------------------
// Flash attention v3 (verified R12, ~90% of mma.sync ceiling): both matmuls
// mma.sync bf16 3-term, FA2 softmax in fragment layout, P in registers.
// ---------------------------------------------------------------------------
#define FL_ROWB 144
#define FL_KHI 0
#define FL_KLO (64 * FL_ROWB)
#define FL_VHI (2 * 64 * FL_ROWB)
#define FL_VLO (3 * 64 * FL_ROWB)
#define FL_BUF (4 * 64 * FL_ROWB)
#define FLASH_SMEM (2 * FL_BUF)

__global__ __launch_bounds__(256, 1)
void flash3(const __nv_bfloat16* __restrict__ Qhi, const __nv_bfloat16* __restrict__ Qlo,
            const __nv_bfloat16* __restrict__ Khi, const __nv_bfloat16* __restrict__ Klo,
            const __nv_bfloat16* __restrict__ Vhi, const __nv_bfloat16* __restrict__ Vlo,
            __nv_bfloat16* __restrict__ OHi, __nv_bfloat16* __restrict__ OLo)
{
    extern __shared__ char smem[];
    const uint32_t sb = smem_u32(smem);
    const int tid = threadIdx.x, lane = tid & 31, wid = tid >> 5;
    const int qbase = blockIdx.x * 128;
    const int hh = blockIdx.y, b = blockIdx.z;
    const size_t base = (size_t)b * SEQ * DMODEL + (size_t)hh * DHEAD;

#pragma unroll
    for (int j = 0; j < 4; j++) {
        int e = tid + 256 * j;
        int row = e >> 3, ch = e & 7;
        size_t g = base + (size_t)(qbase + row) * DMODEL + ch * 8;
        cpasync16(sb + row * FL_ROWB + ch * 16, Qhi + g);
        cpasync16(sb + 18432 + row * FL_ROWB + ch * 16, Qlo + g);
    }
    cp_commit();
    cp_wait0();
    __syncthreads();

    uint32_t qh[4][4], ql[4][4];
    {
        uint32_t ab = sb + (uint32_t)(wid * 16 + (lane & 15)) * FL_ROWB + ((lane >> 4) & 1) * 16;
#pragma unroll
        for (int kc = 0; kc < 4; kc++) {
            ldsm4(qh[kc], ab + kc * 32);
            ldsm4(ql[kc], ab + kc * 32 + 18432);
        }
    }
    __syncthreads();

    auto load_tile = [&](int kt, int bufIdx) {
        const uint32_t bb = sb + bufIdx * FL_BUF;
        const size_t rb = base + (size_t)(kt * 64) * DMODEL;
#pragma unroll
        for (int j = 0; j < 2; j++) {
            int e = tid + 256 * j;
            int row = e >> 3, ch = e & 7;
            size_t g = rb + (size_t)row * DMODEL + ch * 8;
            uint32_t d = bb + row * FL_ROWB + ch * 16;
            cpasync16(d + FL_KHI, Khi + g);
            cpasync16(d + FL_KLO, Klo + g);
            cpasync16(d + FL_VHI, Vhi + g);
            cpasync16(d + FL_VLO, Vlo + g);
        }
        cp_commit();
    };
    load_tile(0, 0);

    float m0 = -1e30f, m1 = -1e30f, l0 = 0.f, l1 = 0.f;
    float o[8][4];
#pragma unroll
    for (int nt = 0; nt < 8; nt++)
#pragma unroll
        for (int e = 0; e < 4; e++) o[nt][e] = 0.f;

    const uint32_t kb_off = (uint32_t)((lane & 7) + ((lane >> 4) & 1) * 8) * FL_ROWB
                          + ((lane >> 3) & 1) * 16;
    const uint32_t vb_off = (uint32_t)(lane & 15) * FL_ROWB
                          + ((lane >> 4) & 1) * 16;

    for (int kt = 0; kt < SEQ / 64; kt++) {
        const int cur = kt & 1;
        if (kt + 1 < SEQ / 64) { load_tile(kt + 1, cur ^ 1); cp_wait1(); }
        else                   { cp_wait0(); }
        __syncthreads();
        const uint32_t bb = sb + cur * FL_BUF;

        float sc[8][4];
#pragma unroll
        for (int nt = 0; nt < 8; nt++)
#pragma unroll
            for (int e = 0; e < 4; e++) sc[nt][e] = 0.f;

#pragma unroll
        for (int kc = 0; kc < 4; kc++) {
#pragma unroll
            for (int p = 0; p < 4; p++) {
                uint32_t bKh[4], bKl[4];
                uint32_t ad = bb + kb_off + (uint32_t)(p * 16) * FL_ROWB + kc * 32;
                ldsm4(bKh, ad + FL_KHI);
                ldsm4(bKl, ad + FL_KLO);
#pragma unroll
                for (int hf = 0; hf < 2; hf++)
                    mma16816(sc[p * 2 + hf], qh[kc], &bKh[hf * 2]);
#pragma unroll
                for (int hf = 0; hf < 2; hf++)
                    mma16816(sc[p * 2 + hf], qh[kc], &bKl[hf * 2]);
#pragma unroll
                for (int hf = 0; hf < 2; hf++)
                    mma16816(sc[p * 2 + hf], ql[kc], &bKh[hf * 2]);
            }
        }

        float rm0 = -1e30f, rm1 = -1e30f;
#pragma unroll
        for (int nt = 0; nt < 8; nt++) {
            rm0 = fmaxf(rm0, fmaxf(sc[nt][0], sc[nt][1]));
            rm1 = fmaxf(rm1, fmaxf(sc[nt][2], sc[nt][3]));
        }
        rm0 = fmaxf(rm0, __shfl_xor_sync(0xffffffffu, rm0, 1));
        rm0 = fmaxf(rm0, __shfl_xor_sync(0xffffffffu, rm0, 2));
        rm1 = fmaxf(rm1, __shfl_xor_sync(0xffffffffu, rm1, 1));
        rm1 = fmaxf(rm1, __shfl_xor_sync(0xffffffffu, rm1, 2));
        float mn0 = fmaxf(m0, rm0), mn1 = fmaxf(m1, rm1);
        float c0 = fexp8(m0 - mn0), c1 = fexp8(m1 - mn1);
        float rs0 = 0.f, rs1 = 0.f;
#pragma unroll
        for (int nt = 0; nt < 8; nt++) {
            sc[nt][0] = fexp8(sc[nt][0] - mn0);
            sc[nt][1] = fexp8(sc[nt][1] - mn0);
            sc[nt][2] = fexp8(sc[nt][2] - mn1);
            sc[nt][3] = fexp8(sc[nt][3] - mn1);
            rs0 += sc[nt][0] + sc[nt][1];
            rs1 += sc[nt][2] + sc[nt][3];
        }
        rs0 += __shfl_xor_sync(0xffffffffu, rs0, 1);
        rs0 += __shfl_xor_sync(0xffffffffu, rs0, 2);
        rs1 += __shfl_xor_sync(0xffffffffu, rs1, 1);
        rs1 += __shfl_xor_sync(0xffffffffu, rs1, 2);
        l0 = l0 * c0 + rs0;  l1 = l1 * c1 + rs1;
        m0 = mn0;  m1 = mn1;
#pragma unroll
        for (int nt = 0; nt < 8; nt++) {
            o[nt][0] *= c0; o[nt][1] *= c0;
            o[nt][2] *= c1; o[nt][3] *= c1;
        }

        uint32_t ph[4][4], pl[4][4];
#pragma unroll
        for (int kc = 0; kc < 4; kc++) {
#pragma unroll
            for (int half = 0; half < 2; half++) {
                const int nt = kc * 2 + half;
#pragma unroll
                for (int rr = 0; rr < 2; rr++) {
                    float p0 = sc[nt][rr * 2 + 0], p1 = sc[nt][rr * 2 + 1];
                    __nv_bfloat16 b0 = __float2bfloat16_rn(p0);
                    __nv_bfloat16 b1 = __float2bfloat16_rn(p1);
                    ph[kc][half * 2 + rr] = pack_bf2(b0, b1);
                    pl[kc][half * 2 + rr] = pack_bf2(
                        __float2bfloat16_rn(p0 - __bfloat162float(b0)),
                        __float2bfloat16_rn(p1 - __bfloat162float(b1)));
                }
            }
        }

#pragma unroll
        for (int kc = 0; kc < 4; kc++) {
#pragma unroll
            for (int dp = 0; dp < 4; dp++) {
                uint32_t vH[4], vL[4];
                uint32_t ad = bb + vb_off + (uint32_t)(kc * 16) * FL_ROWB + dp * 32;
                ldsm4t(vH, ad + FL_VHI);
                ldsm4t(vL, ad + FL_VLO);
#pragma unroll
                for (int hf = 0; hf < 2; hf++)
                    mma16816(o[dp * 2 + hf], ph[kc], &vH[hf * 2]);
#pragma unroll
                for (int hf = 0; hf < 2; hf++)
                    mma16816(o[dp * 2 + hf], ph[kc], &vL[hf * 2]);
#pragma unroll
                for (int hf = 0; hf < 2; hf++)
                    mma16816(o[dp * 2 + hf], pl[kc], &vH[hf * 2]);
            }
        }
        __syncthreads();
    }

    const float i0 = 1.0f / l0, i1 = 1.0f / l1;
    const int r0 = qbase + wid * 16 + (lane >> 2);
#pragma unroll
    for (int nt = 0; nt < 8; nt++) {
        const int col = nt * 8 + (lane & 3) * 2;
        float y00 = o[nt][0] * i0, y01 = o[nt][1] * i0;
        float y10 = o[nt][2] * i1, y11 = o[nt][3] * i1;
        __nv_bfloat16 h00 = __float2bfloat16_rn(y00), h01 = __float2bfloat16_rn(y01);
        __nv_bfloat16 h10 = __float2bfloat16_rn(y10), h11 = __float2bfloat16_rn(y11);
        size_t a0 = base + (size_t)r0 * DMODEL + col;
        size_t a1 = base + (size_t)(r0 + 8) * DMODEL + col;
        *(uint32_t*)(OHi + a0) = pack_bf2(h00, h01);
        *(uint32_t*)(OHi + a1) = pack_bf2(h10, h11);
        *(uint32_t*)(OLo + a0) = pack_bf2(
            __float2bfloat16_rn(y00 - __bfloat162float(h00)),
            __float2bfloat16_rn(y01 - __bfloat162float(h01)));
        *(uint32_t*)(OLo + a1) = pack_bf2(
            __float2bfloat16_rn(y10 - __bfloat162float(h10)),
            __float2bfloat16_rn(y11 - __bfloat162float(h11)));
    }
}

// ---------------------------------------------------------------------------
// Launch. Input order: v, k, q, wq_w, wq_b, wk_w, wk_b, wv_w, wv_b,
//                      dense_w, dense_b
// ---------------------------------------------------------------------------
extern "C" void kernel_launch(void* const* d_in, const int* in_sizes, int n_in,
                              void* d_out, int out_size)
{
    const float* v    = (const float*)d_in[0];
    const float* k    = (const float*)d_in[1];
    const float* q    = (const float*)d_in[2];
    const float* wq_w = (const float*)d_in[3];
    const float* wq_b = (const float*)d_in[4];
    const float* wk_w = (const float*)d_in[5];
    const float* wk_b = (const float*)d_in[6];
    const float* wv_w = (const float*)d_in[7];
    const float* wv_b = (const float*)d_in[8];
    const float* dw   = (const float*)d_in[9];
    const float* db   = (const float*)d_in[10];

    __nv_bfloat16 *xqH, *xqL, *xkH, *xkL, *xvH, *xvL;
    __nv_bfloat16 *wqH, *wqL, *wkH, *wkL, *wvH, *wvL, *wdH, *wdL;
    __nv_bfloat16 *qHi, *qLo, *kHi, *kLo, *vHi, *vLo, *cHi, *cLo;
    cudaGetSymbolAddress((void**)&xqH, g_xqHi); cudaGetSymbolAddress((void**)&xqL, g_xqLo);
    cudaGetSymbolAddress((void**)&xkH, g_xkHi); cudaGetSymbolAddress((void**)&xkL, g_xkLo);
    cudaGetSymbolAddress((void**)&xvH, g_xvHi); cudaGetSymbolAddress((void**)&xvL, g_xvLo);
    cudaGetSymbolAddress((void**)&wqH, g_wqHi); cudaGetSymbolAddress((void**)&wqL, g_wqLo);
    cudaGetSymbolAddress((void**)&wkH, g_wkHi); cudaGetSymbolAddress((void**)&wkL, g_wkLo);
    cudaGetSymbolAddress((void**)&wvH, g_wvHi); cudaGetSymbolAddress((void**)&wvL, g_wvLo);
    cudaGetSymbolAddress((void**)&wdH, g_wdHi); cudaGetSymbolAddress((void**)&wdL, g_wdLo);
    cudaGetSymbolAddress((void**)&qHi, g_qHi);  cudaGetSymbolAddress((void**)&qLo, g_qLo);
    cudaGetSymbolAddress((void**)&kHi, g_kHi);  cudaGetSymbolAddress((void**)&kLo, g_kLo);
    cudaGetSymbolAddress((void**)&vHi, g_vHi);  cudaGetSymbolAddress((void**)&vLo, g_vLo);
    cudaGetSymbolAddress((void**)&cHi, g_cHi);  cudaGetSymbolAddress((void**)&cLo, g_cLo);

    cudaFuncSetAttribute(gemm_mma3, cudaFuncAttributeMaxDynamicSharedMemorySize, GEMM_SMEM);
    cudaFuncSetAttribute(flash3,    cudaFuncAttributeMaxDynamicSharedMemorySize, FLASH_SMEM);

    const int nx4 = MTOT * DMODEL / 4;
    const int nw4 = DMODEL * DMODEL / 4;
    dim3 bt(256);

    // Splits: activations (q,k,v) in one launch; weights (wq,wk,wv,dw) in one
    split3<<<dim3(nx4 / 256, 3), bt>>>(
        SplitArgs{q, xqH, xqL}, SplitArgs{k, xkH, xkL}, SplitArgs{v, xvH, xvL}, nx4);
    split4<<<dim3(nw4 / 256, 4), bt>>>(
        SplitArgs{wq_w, wqH, wqL}, SplitArgs{wk_w, wkH, wkL},
        SplitArgs{wv_w, wvH, wvL}, SplitArgs{dw, wdH, wdL}, nw4);

    // Merged Q/K/V projection GEMMs (grid.z = 3)
    GemmArgs aq{xqH, xqL, wqH, wqL, wq_b, nullptr, qHi, qLo};
    GemmArgs ak{xkH, xkL, wkH, wkL, wk_b, nullptr, kHi, kLo};
    GemmArgs av{xvH, xvL, wvH, wvL, wv_b, nullptr, vHi, vLo};
    gemm_mma3<<<dim3(DMODEL / 128, MTOT / 128, 3), bt, GEMM_SMEM>>>(aq, ak, av);

    // Attention
    dim3 ga(SEQ / 128, NHEAD, BATCH);
    flash3<<<ga, bt, FLASH_SMEM>>>(qHi, qLo, kHi, kLo, vHi, vLo, cHi, cLo);

    // Dense -> fp32 d_out
    GemmArgs ad{cHi, cLo, wdH, wdL, db, (float*)d_out, nullptr, nullptr};
    gemm_mma3<<<dim3(DMODEL / 128, MTOT / 128, 1), bt, GEMM_SMEM>>>(ad, ad, ad);
}

// round 17
// speedup vs baseline: 1.0244x; 1.0244x over previous
#include <cuda_runtime.h>
#include <cuda_bf16.h>
#include <cstdint>

// Problem constants
#define BATCH  4
#define SEQ    2048
#define DMODEL 1024
#define NHEAD  16
#define DHEAD  64
#define MTOT   (BATCH * SEQ)   // 8192 rows
#define KDIM   DMODEL

// ---------------------------------------------------------------------------
// Scratch (__device__ globals — the sanctioned no-alloc path). All bf16 hi/lo.
// ---------------------------------------------------------------------------
__device__ __nv_bfloat16 g_xqHi[(size_t)MTOT * DMODEL];
__device__ __nv_bfloat16 g_xqLo[(size_t)MTOT * DMODEL];
__device__ __nv_bfloat16 g_xkHi[(size_t)MTOT * DMODEL];
__device__ __nv_bfloat16 g_xkLo[(size_t)MTOT * DMODEL];
__device__ __nv_bfloat16 g_xvHi[(size_t)MTOT * DMODEL];
__device__ __nv_bfloat16 g_xvLo[(size_t)MTOT * DMODEL];
__device__ __nv_bfloat16 g_wqHi[(size_t)DMODEL * DMODEL];
__device__ __nv_bfloat16 g_wqLo[(size_t)DMODEL * DMODEL];
__device__ __nv_bfloat16 g_wkHi[(size_t)DMODEL * DMODEL];
__device__ __nv_bfloat16 g_wkLo[(size_t)DMODEL * DMODEL];
__device__ __nv_bfloat16 g_wvHi[(size_t)DMODEL * DMODEL];
__device__ __nv_bfloat16 g_wvLo[(size_t)DMODEL * DMODEL];
__device__ __nv_bfloat16 g_wdHi[(size_t)DMODEL * DMODEL];
__device__ __nv_bfloat16 g_wdLo[(size_t)DMODEL * DMODEL];
__device__ __nv_bfloat16 g_qHi[(size_t)MTOT * DMODEL];
__device__ __nv_bfloat16 g_qLo[(size_t)MTOT * DMODEL];
__device__ __nv_bfloat16 g_kHi[(size_t)MTOT * DMODEL];
__device__ __nv_bfloat16 g_kLo[(size_t)MTOT * DMODEL];
__device__ __nv_bfloat16 g_vHi[(size_t)MTOT * DMODEL];
__device__ __nv_bfloat16 g_vLo[(size_t)MTOT * DMODEL];
__device__ __nv_bfloat16 g_cHi[(size_t)MTOT * DMODEL];
__device__ __nv_bfloat16 g_cLo[(size_t)MTOT * DMODEL];

// ---------------------------------------------------------------------------
// Helpers (baseline compute_103 PTX only — no tcgen05/TMEM in this harness)
// ---------------------------------------------------------------------------
__device__ __forceinline__ uint32_t smem_u32(const void* p) {
    uint32_t a;
    asm("{ .reg .u64 t; cvta.to.shared.u64 t, %1; cvt.u32.u64 %0, t; }"
        : "=r"(a) : "l"(p));
    return a;
}
__device__ __forceinline__ void ldsm4(uint32_t* r, uint32_t addr) {
    asm volatile("ldmatrix.sync.aligned.m8n8.x4.shared.b16 {%0,%1,%2,%3}, [%4];"
                 : "=r"(r[0]), "=r"(r[1]), "=r"(r[2]), "=r"(r[3]) : "r"(addr));
}
__device__ __forceinline__ void ldsm4t(uint32_t* r, uint32_t addr) {
    asm volatile("ldmatrix.sync.aligned.m8n8.x4.trans.shared.b16 {%0,%1,%2,%3}, [%4];"
                 : "=r"(r[0]), "=r"(r[1]), "=r"(r[2]), "=r"(r[3]) : "r"(addr));
}
__device__ __forceinline__ void mma16816(float* d, const uint32_t* a, const uint32_t* b) {
    asm volatile(
        "mma.sync.aligned.m16n8k16.row.col.f32.bf16.bf16.f32 "
        "{%0,%1,%2,%3}, {%4,%5,%6,%7}, {%8,%9}, {%0,%1,%2,%3};"
        : "+f"(d[0]), "+f"(d[1]), "+f"(d[2]), "+f"(d[3])
        : "r"(a[0]), "r"(a[1]), "r"(a[2]), "r"(a[3]), "r"(b[0]), "r"(b[1]));
}
__device__ __forceinline__ uint32_t pack_bf2(__nv_bfloat16 a, __nv_bfloat16 b) {
    __nv_bfloat162 t = __halves2bfloat162(a, b);
    return *(uint32_t*)&t;
}
__device__ __forceinline__ void cpasync16(uint32_t dst, const void* src) {
    asm volatile("cp.async.ca.shared.global [%0], [%1], 16;"
                 :: "r"(dst), "l"(src) : "memory");
}
__device__ __forceinline__ void cp_commit() {
    asm volatile("cp.async.commit_group;" ::: "memory");
}
__device__ __forceinline__ void cp_wait0() {
    asm volatile("cp.async.wait_group 0;" ::: "memory");
}
__device__ __forceinline__ void cp_wait1() {
    asm volatile("cp.async.wait_group 1;" ::: "memory");
}

// exp(x/8) for x <= 0, MUFU-free: 2^(x*log2e/8), deg-4 poly.
__device__ __forceinline__ float fexp8(float x) {
    float t = fmaxf(x * 0.18033688011112043f, -126.0f);
    float r = t + 12582912.0f;
    int   n = __float_as_int(r) - 0x4B400000;
    float f = t - (r - 12582912.0f);
    float p = fmaf(f, 0.0096181291f, 0.0555041087f);
    p = fmaf(f, p, 0.2402265069f);
    p = fmaf(f, p, 0.6931471806f);
    p = fmaf(f, p, 1.0f);
    return __int_as_float((n + 127) << 23) * p;
}

// ---------------------------------------------------------------------------
// fp32 -> (hi, lo) bf16 split: merged launches (blockIdx.y selects operand)
// ---------------------------------------------------------------------------
struct SplitArgs {
    const float* x;
    __nv_bfloat16* hi;
    __nv_bfloat16* lo;
};

__device__ __forceinline__ void split_body(const SplitArgs& s, int i) {
    float4 v = ((const float4*)s.x)[i];
    __nv_bfloat16 h0 = __float2bfloat16_rn(v.x);
    __nv_bfloat16 h1 = __float2bfloat16_rn(v.y);
    __nv_bfloat16 h2 = __float2bfloat16_rn(v.z);
    __nv_bfloat16 h3 = __float2bfloat16_rn(v.w);
    uint2 hv, lv;
    hv.x = pack_bf2(h0, h1);
    hv.y = pack_bf2(h2, h3);
    lv.x = pack_bf2(__float2bfloat16_rn(v.x - __bfloat162float(h0)),
                    __float2bfloat16_rn(v.y - __bfloat162float(h1)));
    lv.y = pack_bf2(__float2bfloat16_rn(v.z - __bfloat162float(h2)),
                    __float2bfloat16_rn(v.w - __bfloat162float(h3)));
    ((uint2*)s.hi)[i] = hv;
    ((uint2*)s.lo)[i] = lv;
}

__global__ __launch_bounds__(256)
void split3(SplitArgs s0, SplitArgs s1, SplitArgs s2, int n4)
{
    int i = blockIdx.x * 256 + threadIdx.x;
    if (i >= n4) return;
    SplitArgs s = (blockIdx.y == 0) ? s0 : ((blockIdx.y == 1) ? s1 : s2);
    split_body(s, i);
}

__global__ __launch_bounds__(256)
void split4(SplitArgs s0, SplitArgs s1, SplitArgs s2, SplitArgs s3, int n4)
{
    int i = blockIdx.x * 256 + threadIdx.x;
    if (i >= n4) return;
    SplitArgs s = (blockIdx.y == 0) ? s0 :
                  ((blockIdx.y == 1) ? s1 : ((blockIdx.y == 2) ? s2 : s3));
    split_body(s, i);
}

// ---------------------------------------------------------------------------
// GEMM via mma.sync bf16 3-term split — R12-verified 2-stage body (96KB smem
// -> 2 CTAs/SM; the R16 3-stage/144KB variant dropped to 1 CTA/SM and was a
// wash). grid.z selects the operand set (merged Q/K/V projections).
// ---------------------------------------------------------------------------
#define GBUF 49152
#define GEMM_SMEM (2 * GBUF)
#define NCHUNK (KDIM / 32)

struct GemmArgs {
    const __nv_bfloat16 *xh, *xl, *wh, *wl;
    const float* bias;
    float* yf;
    __nv_bfloat16 *yh, *yl;
};

__global__ __launch_bounds__(256)
void gemm_mma3(GemmArgs A0, GemmArgs A1, GemmArgs A2)
{
    extern __shared__ char smem[];
    const uint32_t sb = smem_u32(smem);
    GemmArgs ar = (blockIdx.z == 0) ? A0 : ((blockIdx.z == 1) ? A1 : A2);

    const int tid  = threadIdx.x;
    const int lane = tid & 31, wid = tid >> 5;
    const int wm = wid & 3;
    const int wn = wid >> 2;
    const int bm = blockIdx.y * 128, bn = blockIdx.x * 128;

    const int lr = tid >> 1;
    const int h  = tid & 1;
    const size_t rowA = (size_t)(bm + lr) * KDIM;
    const size_t rowB = (size_t)(bn + lr) * KDIM;
    const uint32_t dbase = lr * 48 + h * 16;

    const uint32_t a_off = ((lane & 7) + ((lane >> 3) & 1) * 8) * 48 + ((lane >> 4) & 1) * 16;
    const uint32_t b_off = ((lane & 7) + ((lane >> 4) & 1) * 8) * 48 + ((lane >> 3) & 1) * 16;

    float acc[2][8][4];
#pragma unroll
    for (int mt = 0; mt < 2; mt++)
#pragma unroll
        for (int nt = 0; nt < 8; nt++)
#pragma unroll
            for (int e = 0; e < 4; e++) acc[mt][nt][e] = 0.f;

    auto issue = [&](int c, int bufIdx) {
        const uint32_t bb = sb + bufIdx * GBUF;
        const int k0 = c * 32 + h * 8;
#pragma unroll
        for (int s = 0; s < 2; s++) {
            uint32_t d = bb + s * 6144 + dbase;
            int kk = k0 + s * 16;
            cpasync16(d,         ar.xh + rowA + kk);
            cpasync16(d + 12288, ar.xl + rowA + kk);
            cpasync16(d + 24576, ar.wh + rowB + kk);
            cpasync16(d + 36864, ar.wl + rowB + kk);
        }
        cp_commit();
    };

    issue(0, 0);

    for (int c = 0; c < NCHUNK; c++) {
        cp_wait0();
        __syncthreads();

        if (c + 1 < NCHUNK) issue(c + 1, (c + 1) & 1);

        const uint32_t bufb = sb + (c & 1) * GBUF;
#pragma unroll
        for (int s = 0; s < 2; s++) {
            const uint32_t slab = bufb + s * 6144;
            uint32_t aH[2][4], aL[2][4], bH[4][4], bL[4][4];
#pragma unroll
            for (int mt = 0; mt < 2; mt++) {
                uint32_t ad = slab + (uint32_t)(wm * 32 + mt * 16) * 48 + a_off;
                ldsm4(aH[mt], ad);
                ldsm4(aL[mt], ad + 12288);
            }
#pragma unroll
            for (int p = 0; p < 4; p++) {
                uint32_t bd = slab + 24576 + (uint32_t)(wn * 64 + p * 16) * 48 + b_off;
                ldsm4(bH[p], bd);
                ldsm4(bL[p], bd + 12288);
            }
#pragma unroll
            for (int mt = 0; mt < 2; mt++)
#pragma unroll
                for (int p = 0; p < 4; p++)
#pragma unroll
                    for (int hlf = 0; hlf < 2; hlf++) {
                        const int nt = p * 2 + hlf;
                        mma16816(acc[mt][nt], aH[mt], &bH[p][hlf * 2]);
                        mma16816(acc[mt][nt], aH[mt], &bL[p][hlf * 2]);
                        mma16816(acc[mt][nt], aL[mt], &bH[p][hlf * 2]);
                    }
        }
        __syncthreads();
    }

    const int er = bm + wm * 32 + (lane >> 2);
    const int ec = bn + wn * 64 + (lane & 3) * 2;
#pragma unroll
    for (int mt = 0; mt < 2; mt++)
#pragma unroll
        for (int nt = 0; nt < 8; nt++) {
            int row = er + mt * 16;
            int col = ec + nt * 8;
            float2 bv = *(const float2*)(ar.bias + col);
            float y00 = acc[mt][nt][0] + bv.x, y01 = acc[mt][nt][1] + bv.y;
            float y10 = acc[mt][nt][2] + bv.x, y11 = acc[mt][nt][3] + bv.y;
            if (ar.yf) {
                *(float2*)(ar.yf + (size_t)row * DMODEL + col) = make_float2(y00, y01);
                *(float2*)(ar.yf + (size_t)(row + 8) * DMODEL + col) = make_float2(y10, y11);
            } else {
                __nv_bfloat16 h00 = __float2bfloat16_rn(y00), h01 = __float2bfloat16_rn(y01);
                __nv_bfloat16 h10 = __float2bfloat16_rn(y10), h11 = __float2bfloat16_rn(y11);
                *(uint32_t*)(ar.yh + (size_t)row * DMODEL + col)       = pack_bf2(h00, h01);
                *(uint32_t*)(ar.yh + (size_t)(row + 8) * DMODEL + col) = pack_bf2(h10, h11);
                *(uint32_t*)(ar.yl + (size_t)row * DMODEL + col) = pack_bf2(
                    __float2bfloat16_rn(y00 - __bfloat162float(h00)),
                    __float2bfloat16_rn(y01 - __bfloat162float(h01)));
                *(uint32_t*)(ar.yl + (size_t)(row + 8) * DMODEL + col) = pack_bf2(
                    __float2bfloat16_rn(y10 - __bfloat162float(h10)),
                    __float2bfloat16_rn(y11 - __bfloat162float(h11)));
            }
        }
}

// ---------------------------------------------------------------------------
// Flash attention v4: identical math to R12/R16 flash3 (tensor=59.6% at
// occ=12.5% / 1 CTA/SM), retiled for occupancy: 128-thread CTAs (4 warps),
// q-tile 64, launch_bounds(128,3) -> 2-3 independent CTAs/SM so one CTA's
// softmax overlaps another's MMA. Per-warp work/registers unchanged.
// Smem/CTA: Q staging 18432 (hi@0, lo@9216) then two 36864B K/V buffers.
// ---------------------------------------------------------------------------
#define FL_ROWB 144
#define FL_KHI 0
#define FL_KLO (64 * FL_ROWB)
#define FL_VHI (2 * 64 * FL_ROWB)
#define FL_VLO (3 * 64 * FL_ROWB)
#define FL_BUF (4 * 64 * FL_ROWB)
#define FL_QLO 9216
#define FLASH_SMEM (2 * FL_BUF)

__global__ __launch_bounds__(128, 3)
void flash4(const __nv_bfloat16* __restrict__ Qhi, const __nv_bfloat16* __restrict__ Qlo,
            const __nv_bfloat16* __restrict__ Khi, const __nv_bfloat16* __restrict__ Klo,
            const __nv_bfloat16* __restrict__ Vhi, const __nv_bfloat16* __restrict__ Vlo,
            __nv_bfloat16* __restrict__ OHi, __nv_bfloat16* __restrict__ OLo)
{
    extern __shared__ char smem[];
    const uint32_t sb = smem_u32(smem);
    const int tid = threadIdx.x, lane = tid & 31, wid = tid >> 5;  // wid 0..3
    const int qbase = blockIdx.x * 64;
    const int hh = blockIdx.y, b = blockIdx.z;
    const size_t base = (size_t)b * SEQ * DMODEL + (size_t)hh * DHEAD;

    // ---- Stage Q hi/lo (64 rows), extract A-fragments, then free the region
#pragma unroll
    for (int j = 0; j < 4; j++) {
        int e = tid + 128 * j;           // 0..511
        int row = e >> 3, ch = e & 7;    // 64 rows x 8 chunks(16B)
        size_t g = base + (size_t)(qbase + row) * DMODEL + ch * 8;
        cpasync16(sb + row * FL_ROWB + ch * 16, Qhi + g);
        cpasync16(sb + FL_QLO + row * FL_ROWB + ch * 16, Qlo + g);
    }
    cp_commit();
    cp_wait0();
    __syncthreads();

    uint32_t qh[4][4], ql[4][4];
    {
        uint32_t ab = sb + (uint32_t)(wid * 16 + (lane & 15)) * FL_ROWB + ((lane >> 4) & 1) * 16;
#pragma unroll
        for (int kc = 0; kc < 4; kc++) {
            ldsm4(qh[kc], ab + kc * 32);
            ldsm4(ql[kc], ab + kc * 32 + FL_QLO);
        }
    }
    __syncthreads();   // Q region becomes K/V buf0

    auto load_tile = [&](int kt, int bufIdx) {
        const uint32_t bb = sb + bufIdx * FL_BUF;
        const size_t rb = base + (size_t)(kt * 64) * DMODEL;
#pragma unroll
        for (int j = 0; j < 4; j++) {
            int e = tid + 128 * j;       // 0..511
            int row = e >> 3, ch = e & 7;
            size_t g = rb + (size_t)row * DMODEL + ch * 8;
            uint32_t d = bb + row * FL_ROWB + ch * 16;
            cpasync16(d + FL_KHI, Khi + g);
            cpasync16(d + FL_KLO, Klo + g);
            cpasync16(d + FL_VHI, Vhi + g);
            cpasync16(d + FL_VLO, Vlo + g);
        }
        cp_commit();
    };
    load_tile(0, 0);

    float m0 = -1e30f, m1 = -1e30f, l0 = 0.f, l1 = 0.f;
    float o[8][4];
#pragma unroll
    for (int nt = 0; nt < 8; nt++)
#pragma unroll
        for (int e = 0; e < 4; e++) o[nt][e] = 0.f;

    const uint32_t kb_off = (uint32_t)((lane & 7) + ((lane >> 4) & 1) * 8) * FL_ROWB
                          + ((lane >> 3) & 1) * 16;
    const uint32_t vb_off = (uint32_t)(lane & 15) * FL_ROWB
                          + ((lane >> 4) & 1) * 16;

    for (int kt = 0; kt < SEQ / 64; kt++) {
        const int cur = kt & 1;
        if (kt + 1 < SEQ / 64) { load_tile(kt + 1, cur ^ 1); cp_wait1(); }
        else                   { cp_wait0(); }
        __syncthreads();
        const uint32_t bb = sb + cur * FL_BUF;

        // ---- S = Q @ K^T (3-term), S in D-fragments sc[nt][0..3]
        float sc[8][4];
#pragma unroll
        for (int nt = 0; nt < 8; nt++)
#pragma unroll
            for (int e = 0; e < 4; e++) sc[nt][e] = 0.f;

#pragma unroll
        for (int kc = 0; kc < 4; kc++) {
#pragma unroll
            for (int p = 0; p < 4; p++) {
                uint32_t bKh[4], bKl[4];
                uint32_t ad = bb + kb_off + (uint32_t)(p * 16) * FL_ROWB + kc * 32;
                ldsm4(bKh, ad + FL_KHI);
                ldsm4(bKl, ad + FL_KLO);
#pragma unroll
                for (int hf = 0; hf < 2; hf++)
                    mma16816(sc[p * 2 + hf], qh[kc], &bKh[hf * 2]);
#pragma unroll
                for (int hf = 0; hf < 2; hf++)
                    mma16816(sc[p * 2 + hf], qh[kc], &bKl[hf * 2]);
#pragma unroll
                for (int hf = 0; hf < 2; hf++)
                    mma16816(sc[p * 2 + hf], ql[kc], &bKh[hf * 2]);
            }
        }

        // ---- Online softmax in fragment layout (rows r0 = l>>2, r1 = r0+8)
        float rm0 = -1e30f, rm1 = -1e30f;
#pragma unroll
        for (int nt = 0; nt < 8; nt++) {
            rm0 = fmaxf(rm0, fmaxf(sc[nt][0], sc[nt][1]));
            rm1 = fmaxf(rm1, fmaxf(sc[nt][2], sc[nt][3]));
        }
        rm0 = fmaxf(rm0, __shfl_xor_sync(0xffffffffu, rm0, 1));
        rm0 = fmaxf(rm0, __shfl_xor_sync(0xffffffffu, rm0, 2));
        rm1 = fmaxf(rm1, __shfl_xor_sync(0xffffffffu, rm1, 1));
        rm1 = fmaxf(rm1, __shfl_xor_sync(0xffffffffu, rm1, 2));
        float mn0 = fmaxf(m0, rm0), mn1 = fmaxf(m1, rm1);
        float c0 = fexp8(m0 - mn0), c1 = fexp8(m1 - mn1);
        float rs0 = 0.f, rs1 = 0.f;
#pragma unroll
        for (int nt = 0; nt < 8; nt++) {
            sc[nt][0] = fexp8(sc[nt][0] - mn0);
            sc[nt][1] = fexp8(sc[nt][1] - mn0);
            sc[nt][2] = fexp8(sc[nt][2] - mn1);
            sc[nt][3] = fexp8(sc[nt][3] - mn1);
            rs0 += sc[nt][0] + sc[nt][1];
            rs1 += sc[nt][2] + sc[nt][3];
        }
        rs0 += __shfl_xor_sync(0xffffffffu, rs0, 1);
        rs0 += __shfl_xor_sync(0xffffffffu, rs0, 2);
        rs1 += __shfl_xor_sync(0xffffffffu, rs1, 1);
        rs1 += __shfl_xor_sync(0xffffffffu, rs1, 2);
        l0 = l0 * c0 + rs0;  l1 = l1 * c1 + rs1;
        m0 = mn0;  m1 = mn1;
#pragma unroll
        for (int nt = 0; nt < 8; nt++) {
            o[nt][0] *= c0; o[nt][1] *= c0;
            o[nt][2] *= c1; o[nt][3] *= c1;
        }

        // ---- Pack P: S D-fragment == P A-fragment (hi/lo)
        uint32_t ph[4][4], pl[4][4];
#pragma unroll
        for (int kc = 0; kc < 4; kc++) {
#pragma unroll
            for (int half = 0; half < 2; half++) {
                const int nt = kc * 2 + half;
#pragma unroll
                for (int rr = 0; rr < 2; rr++) {
                    float p0 = sc[nt][rr * 2 + 0], p1 = sc[nt][rr * 2 + 1];
                    __nv_bfloat16 b0 = __float2bfloat16_rn(p0);
                    __nv_bfloat16 b1 = __float2bfloat16_rn(p1);
                    ph[kc][half * 2 + rr] = pack_bf2(b0, b1);
                    pl[kc][half * 2 + rr] = pack_bf2(
                        __float2bfloat16_rn(p0 - __bfloat162float(b0)),
                        __float2bfloat16_rn(p1 - __bfloat162float(b1)));
                }
            }
        }

        // ---- O += P @ V (3-term), V via ldmatrix.trans on natural [s][d]
#pragma unroll
        for (int kc = 0; kc < 4; kc++) {
#pragma unroll
            for (int dp = 0; dp < 4; dp++) {
                uint32_t vH[4], vL[4];
                uint32_t ad = bb + vb_off + (uint32_t)(kc * 16) * FL_ROWB + dp * 32;
                ldsm4t(vH, ad + FL_VHI);
                ldsm4t(vL, ad + FL_VLO);
#pragma unroll
                for (int hf = 0; hf < 2; hf++)
                    mma16816(o[dp * 2 + hf], ph[kc], &vH[hf * 2]);
#pragma unroll
                for (int hf = 0; hf < 2; hf++)
                    mma16816(o[dp * 2 + hf], ph[kc], &vL[hf * 2]);
#pragma unroll
                for (int hf = 0; hf < 2; hf++)
                    mma16816(o[dp * 2 + hf], pl[kc], &vH[hf * 2]);
            }
        }
        __syncthreads();   // all ldsm done before next tile overwrites buf
    }

    // ---- Normalize, split hi/lo, store ctx (merged [B,S,D] layout)
    const float i0 = 1.0f / l0, i1 = 1.0f / l1;
    const int r0 = qbase + wid * 16 + (lane >> 2);
#pragma unroll
    for (int nt = 0; nt < 8; nt++) {
        const int col = nt * 8 + (lane & 3) * 2;
        float y00 = o[nt][0] * i0, y01 = o[nt][1] * i0;
        float y10 = o[nt][2] * i1, y11 = o[nt][3] * i1;
        __nv_bfloat16 h00 = __float2bfloat16_rn(y00), h01 = __float2bfloat16_rn(y01);
        __nv_bfloat16 h10 = __float2bfloat16_rn(y10), h11 = __float2bfloat16_rn(y11);
        size_t a0 = base + (size_t)r0 * DMODEL + col;
        size_t a1 = base + (size_t)(r0 + 8) * DMODEL + col;
        *(uint32_t*)(OHi + a0) = pack_bf2(h00, h01);
        *(uint32_t*)(OHi + a1) = pack_bf2(h10, h11);
        *(uint32_t*)(OLo + a0) = pack_bf2(
            __float2bfloat16_rn(y00 - __bfloat162float(h00)),
            __float2bfloat16_rn(y01 - __bfloat162float(h01)));
        *(uint32_t*)(OLo + a1) = pack_bf2(
            __float2bfloat16_rn(y10 - __bfloat162float(h10)),
            __float2bfloat16_rn(y11 - __bfloat162float(h11)));
    }
}

// ---------------------------------------------------------------------------
// Launch. Input order: v, k, q, wq_w, wq_b, wk_w, wk_b, wv_w, wv_b,
//                      dense_w, dense_b
// ---------------------------------------------------------------------------
extern "C" void kernel_launch(void* const* d_in, const int* in_sizes, int n_in,
                              void* d_out, int out_size)
{
    const float* v    = (const float*)d_in[0];
    const float* k    = (const float*)d_in[1];
    const float* q    = (const float*)d_in[2];
    const float* wq_w = (const float*)d_in[3];
    const float* wq_b = (const float*)d_in[4];
    const float* wk_w = (const float*)d_in[5];
    const float* wk_b = (const float*)d_in[6];
    const float* wv_w = (const float*)d_in[7];
    const float* wv_b = (const float*)d_in[8];
    const float* dw   = (const float*)d_in[9];
    const float* db   = (const float*)d_in[10];

    __nv_bfloat16 *xqH, *xqL, *xkH, *xkL, *xvH, *xvL;
    __nv_bfloat16 *wqH, *wqL, *wkH, *wkL, *wvH, *wvL, *wdH, *wdL;
    __nv_bfloat16 *qHi, *qLo, *kHi, *kLo, *vHi, *vLo, *cHi, *cLo;
    cudaGetSymbolAddress((void**)&xqH, g_xqHi); cudaGetSymbolAddress((void**)&xqL, g_xqLo);
    cudaGetSymbolAddress((void**)&xkH, g_xkHi); cudaGetSymbolAddress((void**)&xkL, g_xkLo);
    cudaGetSymbolAddress((void**)&xvH, g_xvHi); cudaGetSymbolAddress((void**)&xvL, g_xvLo);
    cudaGetSymbolAddress((void**)&wqH, g_wqHi); cudaGetSymbolAddress((void**)&wqL, g_wqLo);
    cudaGetSymbolAddress((void**)&wkH, g_wkHi); cudaGetSymbolAddress((void**)&wkL, g_wkLo);
    cudaGetSymbolAddress((void**)&wvH, g_wvHi); cudaGetSymbolAddress((void**)&wvL, g_wvLo);
    cudaGetSymbolAddress((void**)&wdH, g_wdHi); cudaGetSymbolAddress((void**)&wdL, g_wdLo);
    cudaGetSymbolAddress((void**)&qHi, g_qHi);  cudaGetSymbolAddress((void**)&qLo, g_qLo);
    cudaGetSymbolAddress((void**)&kHi, g_kHi);  cudaGetSymbolAddress((void**)&kLo, g_kLo);
    cudaGetSymbolAddress((void**)&vHi, g_vHi);  cudaGetSymbolAddress((void**)&vLo, g_vLo);
    cudaGetSymbolAddress((void**)&cHi, g_cHi);  cudaGetSymbolAddress((void**)&cLo, g_cLo);

    cudaFuncSetAttribute(gemm_mma3, cudaFuncAttributeMaxDynamicSharedMemorySize, GEMM_SMEM);
    cudaFuncSetAttribute(flash4,    cudaFuncAttributeMaxDynamicSharedMemorySize, FLASH_SMEM);

    const int nx4 = MTOT * DMODEL / 4;
    const int nw4 = DMODEL * DMODEL / 4;
    dim3 bt(256);

    // Splits: activations (q,k,v) in one launch; weights (wq,wk,wv,dw) in one
    split3<<<dim3(nx4 / 256, 3), bt>>>(
        SplitArgs{q, xqH, xqL}, SplitArgs{k, xkH, xkL}, SplitArgs{v, xvH, xvL}, nx4);
    split4<<<dim3(nw4 / 256, 4), bt>>>(
        SplitArgs{wq_w, wqH, wqL}, SplitArgs{wk_w, wkH, wkL},
        SplitArgs{wv_w, wvH, wvL}, SplitArgs{dw, wdH, wdL}, nw4);

    // Merged Q/K/V projection GEMMs (grid.z = 3)
    GemmArgs aq{xqH, xqL, wqH, wqL, wq_b, nullptr, qHi, qLo};
    GemmArgs ak{xkH, xkL, wkH, wkL, wk_b, nullptr, kHi, kLo};
    GemmArgs av{xvH, xvL, wvH, wvL, wv_b, nullptr, vHi, vLo};
    gemm_mma3<<<dim3(DMODEL / 128, MTOT / 128, 3), bt, GEMM_SMEM>>>(aq, ak, av);

    // Attention: 128-thread CTAs, q-tile 64, 2-3 CTAs/SM
    dim3 ga(SEQ / 64, NHEAD, BATCH);
    flash4<<<ga, dim3(128), FLASH_SMEM>>>(qHi, qLo, kHi, kLo, vHi, vLo, cHi, cLo);

    // Dense -> fp32 d_out
    GemmArgs ad{cHi, cLo, wdH, wdL, db, (float*)d_out, nullptr, nullptr};
    gemm_mma3<<<dim3(DMODEL / 128, MTOT / 128, 1), bt, GEMM_SMEM>>>(ad, ad, ad);
}